// round 16
// baseline (speedup 1.0000x reference)
#include <cuda_runtime.h>
#include <cuda_fp16.h>
#include <cstdint>

// Problem constants (RecCore: B=8192, D=2048, H=2048, 10 iterations)
#define MB_  8192
#define HH_  2048
#define K3_  (3 * HH_)
#define NITER 10

#define BM 128
#define BNG 64                    // per-gate N tile
#define NSTK 192                  // stacked B rows (3 gates * 64)
#define BK 64                     // fp16 elems per chunk row = 128 bytes
#define NC 32                     // 2048 / 64
#define NTH 256
#define STAGE_BYTES ((BM + NSTK) * 128)   // 40960
#define SMEM_TOTAL (2 * STAGE_BYTES)      // 81920 -> 2 CTAs/SM

// Scratch
// gi interleaved: slot (m, n2) holds {r_h2, z_h2, n_h2, pad} = 16B; n2 = n/2 (0..1023)
__device__ uint4  g_gi[(long long)MB_ * (HH_ / 2)];
__device__ __half g_h16[2][(long long)MB_ * HH_];
__device__ __half g_w16i[(long long)K3_ * HH_];
__device__ __half g_w16h[(long long)K3_ * HH_];
__device__ __half g_e16[(long long)MB_ * HH_];

__device__ __forceinline__ uint32_t smem_u32(const void* p) {
    return (uint32_t)__cvta_generic_to_shared(p);
}
__device__ __forceinline__ void cp16(uint32_t s, const void* g) {
    asm volatile("cp.async.cg.shared.global [%0], [%1], 16;\n" :: "r"(s), "l"(g));
}
__device__ __forceinline__ float tanha(float x) {
    float y;
    asm("tanh.approx.f32 %0, %1;" : "=f"(y) : "f"(x));
    return y;
}
__device__ __forceinline__ float sigf(float x) {
    return 0.5f + 0.5f * tanha(0.5f * x);
}
__device__ __forceinline__ void ldsm4(uint32_t* r, uint32_t addr) {
    asm volatile("ldmatrix.sync.aligned.m8n8.x4.shared.b16 {%0,%1,%2,%3}, [%4];"
                 : "=r"(r[0]), "=r"(r[1]), "=r"(r[2]), "=r"(r[3]) : "r"(addr));
}
__device__ __forceinline__ void mma16816(float* c, const uint32_t* a, uint32_t b0, uint32_t b1) {
    asm volatile(
        "mma.sync.aligned.m16n8k16.row.col.f32.f16.f16.f32 "
        "{%0,%1,%2,%3}, {%4,%5,%6,%7}, {%8,%9}, {%0,%1,%2,%3};\n"
        : "+f"(c[0]), "+f"(c[1]), "+f"(c[2]), "+f"(c[3])
        : "r"(a[0]), "r"(a[1]), "r"(a[2]), "r"(a[3]), "r"(b0), "r"(b1));
}
__device__ __forceinline__ uint32_t swz(uint32_t off) {
    return off ^ ((off >> 3) & 0x70);
}
__device__ __forceinline__ uint32_t h2u(__half2 h) {
    return *reinterpret_cast<uint32_t*>(&h);
}
__device__ __forceinline__ __half2 u2h(uint32_t u) {
    return *reinterpret_cast<__half2*>(&u);
}
__device__ __forceinline__ void pfL2(const void* p) {
    asm volatile("prefetch.global.L2 [%0];" :: "l"(p));
}

// Fused 3-gate fp16 GEMM (HMMA m16n8k16 + ldmatrix), fp32 accumulate.
// 256 threads, 2 CTAs/SM. CTA tile: M=128 x (64 per gate).
// Warp tile: 64m x 16n per gate (2 m-warps x 4 n-warps) -> 7 LDSM / 24 MMA per k16.
// NO k-stagger (R12 showed it wrecks cross-CTA L2 locality).
// Fragment smem addresses precomputed; per-k16-step address = base ^ (s<<5).
// MODE 0: gi (interleaved) = acc + b_ih  AND  h16 out = GRU step with h=0 (fused iter0)
// MODE 1: GRU step, intermediate: write h16 only
// MODE 2: GRU step, final: write fp32 out only
template <int MODE>
__global__ void __launch_bounds__(NTH, 2)
gru_h(const __half* __restrict__ A16,    // [8192, 2048]  (e16 or h16_in)
      const __half* __restrict__ W16,    // [6144, 2048]
      const float*  __restrict__ b_ih,   // [6144]  (MODE 0)
      const float*  __restrict__ b_hh,   // [6144]
      uint4*        __restrict__ gi,     // written MODE 0, read MODE 1/2
      float*        __restrict__ outf,   // MODE 2
      __half*       __restrict__ out16)  // MODE 0/1
{
    extern __shared__ char smc[];
    const uint32_t sbase = smem_u32(smc);
    const int t = threadIdx.x;
    const int wid = t >> 5, lane = t & 31;
    const int m0 = blockIdx.y * BM;
    const int n0 = blockIdx.x * BNG;
    const int wm  = (wid >> 2) * 64;     // warp m offset (0, 64)
    const int wn2 = (wid & 3) * 16;      // warp n offset within gate (0,16,32,48)
    const int lr = lane >> 2;            // 0..7
    const int lc = lane & 3;             // 0..3

    float acc2[3][4][2][4];              // [gate][m-frag][n8][4]
#pragma unroll
    for (int g = 0; g < 3; g++)
#pragma unroll
        for (int i = 0; i < 4; i++)
#pragma unroll
            for (int j = 0; j < 2; j++)
#pragma unroll
                for (int c = 0; c < 4; c++) acc2[g][i][j][c] = 0.0f;

    // ---- precomputed swizzled smem offsets ----
    uint32_t soff[10];
#pragma unroll
    for (int i = 0; i < 10; i++) {
        int id = t + NTH * i;
        int row = id >> 3;
        int qb = (id & 7) * 16;
        soff[i] = swz((uint32_t)row * 128 + qb);
    }

    // ldmatrix lane addressing
    const int a_row = lane & 15;
    const int a_kb  = (lane >> 4) * 16;
    const int b_row = (lane & 7) | ((lane & 16) >> 1);
    const int b_kb  = (lane & 8) * 2;

    uint32_t aoff[4], boff[3];
#pragma unroll
    for (int i = 0; i < 4; i++)
        aoff[i] = swz((uint32_t)(wm + i * 16 + a_row) * 128 + a_kb);
#pragma unroll
    for (int g = 0; g < 3; g++)
        boff[g] = swz((uint32_t)(BM + g * BNG + wn2 + b_row) * 128 + b_kb);

    auto issue = [&](int stage, int kc) {   // kc in fp16 elems
        uint32_t st = sbase + stage * STAGE_BYTES;
#pragma unroll
        for (int i = 0; i < 10; i++) {
            int id = t + NTH * i;          // 0..2559
            int row = id >> 3;             // 0..319
            int qb = (id & 7) * 16;        // byte offset in row
            const __half* gsrc;
            if (row < BM) {
                gsrc = A16 + (size_t)(m0 + row) * HH_ + kc + (qb >> 1);
            } else {
                int r = row - BM;
                int g = r >> 6, n = r & 63;
                gsrc = W16 + ((size_t)g * HH_ + n0 + n) * HH_ + kc + (qb >> 1);
            }
            cp16(st + soff[i], gsrc);
        }
        asm volatile("cp.async.commit_group;\n" ::: "memory");
    };

    issue(0, 0);

    for (int c = 0; c < NC; c++) {
        asm volatile("cp.async.wait_group 0;\n" ::: "memory");
        __syncthreads();

        // L2 prefetch of epilogue operands, issued once, well before the tail
        if (MODE != 0 && c == NC - 4) {
#pragma unroll
            for (int j2 = 0; j2 < 2; j2++) {
                int ngl = n0 + wn2 + j2 * 8 + 2 * lc;
#pragma unroll
                for (int i = 0; i < 4; i++) {
                    int m = m0 + wm + i * 16 + lr;
#pragma unroll
                    for (int half = 0; half < 2; half++) {
                        int mm = m + half * 8;
                        pfL2(gi + (size_t)mm * (HH_ / 2) + (ngl >> 1));
                        pfL2(A16 + (size_t)mm * HH_ + ngl);
                    }
                }
            }
        }

        uint32_t st = sbase + (c & 1) * STAGE_BYTES;

        // chunk-start fragment loads
        uint32_t a[4][4];                 // 4 m-frags, single-buffered, in-place reload
        uint32_t b[2][4];                 // B double-buffered
#pragma unroll
        for (int i = 0; i < 4; i++) ldsm4(a[i], st + aoff[i]);
        ldsm4(b[0], st + boff[0]);

#pragma unroll
        for (int s = 0; s < 4; s++) {
            const uint32_t sx  = (uint32_t)(s << 5);
            const uint32_t sx1 = (uint32_t)((s + 1) << 5);
#pragma unroll
            for (int g = 0; g < 3; g++) {
                const int bi = (s * 3 + g) & 1;
                // prefetch next B fragment group (crossing step boundary)
                if (g < 2)       ldsm4(b[bi ^ 1], st + (boff[g + 1] ^ sx));
                else if (s < 3)  ldsm4(b[bi ^ 1], st + (boff[0] ^ sx1));
#pragma unroll
                for (int i = 0; i < 4; i++) {
                    mma16816(acc2[g][i][0], a[i], b[bi][0], b[bi][1]);
                    mma16816(acc2[g][i][1], a[i], b[bi][2], b[bi][3]);
                    // last gate: a[i] had its final use this step -> reload in place
                    if (g == 2 && s < 3) ldsm4(a[i], st + (aoff[i] ^ sx1));
                }
            }
            // overlap the next chunk's cp.async issue burst with the MMA stream
            if (s == 0 && c + 1 < NC) issue((c + 1) & 1, (c + 1) * BK);
        }
    }

    // ---------------- Epilogue ----------------
#pragma unroll
    for (int j2 = 0; j2 < 2; j2++) {
        int ngl = n0 + wn2 + j2 * 8 + 2 * lc;     // global per-gate col (even)
        float2 bhr = *(const float2*)(b_hh + ngl);
        float2 bhz = *(const float2*)(b_hh + HH_ + ngl);
        float2 bhn = *(const float2*)(b_hh + 2 * HH_ + ngl);
        float2 bir, biz, bin;
        if (MODE == 0) {
            bir = *(const float2*)(b_ih + ngl);
            biz = *(const float2*)(b_ih + HH_ + ngl);
            bin = *(const float2*)(b_ih + 2 * HH_ + ngl);
        }
#pragma unroll
        for (int i = 0; i < 4; i++) {
            int m = m0 + wm + i * 16 + lr;
#pragma unroll
            for (int half = 0; half < 2; half++) {
                int mm = m + half * 8;
                int o  = half * 2;
                size_t slot = (size_t)mm * (HH_ / 2) + (ngl >> 1);

                if (MODE == 0) {
                    float grx = acc2[0][i][j2][o]     + bir.x;
                    float gry = acc2[0][i][j2][o + 1] + bir.y;
                    float gzx = acc2[1][i][j2][o]     + biz.x;
                    float gzy = acc2[1][i][j2][o + 1] + biz.y;
                    float gnx = acc2[2][i][j2][o]     + bin.x;
                    float gny = acc2[2][i][j2][o + 1] + bin.y;
                    uint4 v;
                    v.x = h2u(__floats2half2_rn(grx, gry));
                    v.y = h2u(__floats2half2_rn(gzx, gzy));
                    v.z = h2u(__floats2half2_rn(gnx, gny));
                    v.w = 0u;
                    gi[slot] = v;
                    // fused iteration 0 (h = 0)
                    float rx = sigf(grx + bhr.x), ry = sigf(gry + bhr.y);
                    float zx = sigf(gzx + bhz.x), zy = sigf(gzy + bhz.y);
                    float nx = tanha(gnx + rx * bhn.x);
                    float ny = tanha(gny + ry * bhn.y);
                    float hx = (1.0f - zx) * nx;
                    float hy = (1.0f - zy) * ny;
                    *(__half2*)(out16 + (size_t)mm * HH_ + ngl) = __floats2half2_rn(hx, hy);
                } else {
                    uint4 v = gi[slot];
                    float2 gr = __half22float2(u2h(v.x));
                    float2 gz = __half22float2(u2h(v.y));
                    float2 gn = __half22float2(u2h(v.z));
                    float2 hv = __half22float2(*(const __half2*)(A16 + (size_t)mm * HH_ + ngl));

                    float rx = sigf(gr.x + acc2[0][i][j2][o]     + bhr.x);
                    float ry = sigf(gr.y + acc2[0][i][j2][o + 1] + bhr.y);
                    float zx = sigf(gz.x + acc2[1][i][j2][o]     + bhz.x);
                    float zy = sigf(gz.y + acc2[1][i][j2][o + 1] + bhz.y);
                    float nx = tanha(gn.x + rx * (acc2[2][i][j2][o]     + bhn.x));
                    float ny = tanha(gn.y + ry * (acc2[2][i][j2][o + 1] + bhn.y));

                    float hx = nx + zx * (hv.x - nx);
                    float hy = ny + zy * (hv.y - ny);

                    if (MODE == 1) {
                        *(__half2*)(out16 + (size_t)mm * HH_ + ngl) = __floats2half2_rn(hx, hy);
                    } else {
                        *(float2*)(outf + (size_t)mm * HH_ + ngl) = make_float2(hx, hy);
                    }
                }
            }
        }
    }
}

// merged float -> half conversion for 3 tensors (single launch)
__global__ void f2h3_kernel(const float* __restrict__ s0, __half* __restrict__ d0, int n0,
                            const float* __restrict__ s1, __half* __restrict__ d1, int n1,
                            const float* __restrict__ s2, __half* __restrict__ d2, int n2)
{
    int j = blockIdx.x * blockDim.x + threadIdx.x;
    const float* s;
    __half* d;
    if (j < n0) { s = s0; d = d0; }
    else if ((j -= n0) < n1) { s = s1; d = d1; }
    else if ((j -= n1) < n2) { s = s2; d = d2; }
    else return;
    float4 v = ((const float4*)s)[j];
    ((__half2*)d)[2 * j]     = __floats2half2_rn(v.x, v.y);
    ((__half2*)d)[2 * j + 1] = __floats2half2_rn(v.z, v.w);
}

extern "C" void kernel_launch(void* const* d_in, const int* in_sizes, int n_in,
                              void* d_out, int out_size)
{
    const float* enc  = (const float*)d_in[0];
    const float* w_ih = (const float*)d_in[1];
    const float* w_hh = (const float*)d_in[2];
    const float* b_ih = (const float*)d_in[3];
    const float* b_hh = (const float*)d_in[4];
    float* out = (float*)d_out;

    cudaFuncSetAttribute(gru_h<0>, cudaFuncAttributeMaxDynamicSharedMemorySize, SMEM_TOTAL);
    cudaFuncSetAttribute(gru_h<1>, cudaFuncAttributeMaxDynamicSharedMemorySize, SMEM_TOTAL);
    cudaFuncSetAttribute(gru_h<2>, cudaFuncAttributeMaxDynamicSharedMemorySize, SMEM_TOTAL);

    uint4* gi;
    __half *h16, *w16i, *w16h, *e16;
    cudaGetSymbolAddress((void**)&gi,   g_gi);
    cudaGetSymbolAddress((void**)&h16,  g_h16);
    cudaGetSymbolAddress((void**)&w16i, g_w16i);
    cudaGetSymbolAddress((void**)&w16h, g_w16h);
    cudaGetSymbolAddress((void**)&e16,  g_e16);
    const size_t HN = (size_t)MB_ * HH_;

    dim3 grid(HH_ / BNG, MB_ / BM);   // (32, 64) = 2048 CTAs

    // convert all operands upfront in one launch
    const int n0 = MB_ * HH_ / 4;        // enc float4s
    const int n1 = K3_ * HH_ / 4;        // w_ih float4s
    const int n2 = K3_ * HH_ / 4;        // w_hh float4s
    f2h3_kernel<<<(n0 + n1 + n2 + 255) / 256, 256>>>(enc, e16, n0,
                                                     w_ih, w16i, n1,
                                                     w_hh, w16h, n2);

    // gi = enc @ w_ih^T + b_ih  (interleaved fp16), fused with iteration 0 -> h16[0]
    gru_h<0><<<grid, NTH, SMEM_TOTAL>>>(e16, w16i, b_ih, b_hh, gi, nullptr, h16);

    // iterations 1..8 (write h16), iteration 9 (write fp32 out)
    int p = 0;
    for (int it = 1; it < NITER - 1; it++) {
        gru_h<1><<<grid, NTH, SMEM_TOTAL>>>(h16 + p * HN, w16h, b_ih, b_hh, gi,
                                            nullptr, h16 + (1 - p) * HN);
        p = 1 - p;
    }
    gru_h<2><<<grid, NTH, SMEM_TOTAL>>>(h16 + p * HN, w16h, b_ih, b_hh, gi, out, nullptr);
}

// round 17
// speedup vs baseline: 1.1507x; 1.1507x over previous
#include <cuda_runtime.h>
#include <cuda_fp16.h>
#include <cstdint>

// Problem constants (RecCore: B=8192, D=2048, H=2048, 10 iterations)
#define MB_  8192
#define HH_  2048
#define K3_  (3 * HH_)
#define NITER 10

#define BM 128
#define BNG 64                    // per-gate N tile
#define NSTK 192                  // stacked B rows (3 gates * 64)
#define BK 64                     // fp16 elems per chunk row = 128 bytes
#define NC 32                     // 2048 / 64
#define NTH 256
#define STAGE_BYTES ((BM + NSTK) * 128)   // 40960
#define SMEM_TOTAL (2 * STAGE_BYTES)      // 81920 -> 2 CTAs/SM

// Scratch
// gi interleaved: slot (m, n2) holds {r_h2, z_h2, n_h2, pad} = 16B; n2 = n/2 (0..1023)
__device__ uint4  g_gi[(long long)MB_ * (HH_ / 2)];
__device__ __half g_h16[2][(long long)MB_ * HH_];
__device__ __half g_w16i[(long long)K3_ * HH_];
__device__ __half g_w16h[(long long)K3_ * HH_];
__device__ __half g_e16[(long long)MB_ * HH_];

__device__ __forceinline__ uint32_t smem_u32(const void* p) {
    return (uint32_t)__cvta_generic_to_shared(p);
}
__device__ __forceinline__ void cp16(uint32_t s, const void* g) {
    asm volatile("cp.async.cg.shared.global [%0], [%1], 16;\n" :: "r"(s), "l"(g));
}
__device__ __forceinline__ float tanha(float x) {
    float y;
    asm("tanh.approx.f32 %0, %1;" : "=f"(y) : "f"(x));
    return y;
}
__device__ __forceinline__ float sigf(float x) {
    return 0.5f + 0.5f * tanha(0.5f * x);
}
__device__ __forceinline__ void ldsm4(uint32_t* r, uint32_t addr) {
    asm volatile("ldmatrix.sync.aligned.m8n8.x4.shared.b16 {%0,%1,%2,%3}, [%4];"
                 : "=r"(r[0]), "=r"(r[1]), "=r"(r[2]), "=r"(r[3]) : "r"(addr));
}
__device__ __forceinline__ void mma16816(float* c, const uint32_t* a, uint32_t b0, uint32_t b1) {
    asm volatile(
        "mma.sync.aligned.m16n8k16.row.col.f32.f16.f16.f32 "
        "{%0,%1,%2,%3}, {%4,%5,%6,%7}, {%8,%9}, {%0,%1,%2,%3};\n"
        : "+f"(c[0]), "+f"(c[1]), "+f"(c[2]), "+f"(c[3])
        : "r"(a[0]), "r"(a[1]), "r"(a[2]), "r"(a[3]), "r"(b0), "r"(b1));
}
__device__ __forceinline__ uint32_t swz(uint32_t off) {
    return off ^ ((off >> 3) & 0x70);
}
__device__ __forceinline__ uint32_t h2u(__half2 h) {
    return *reinterpret_cast<uint32_t*>(&h);
}
__device__ __forceinline__ __half2 u2h(uint32_t u) {
    return *reinterpret_cast<__half2*>(&u);
}
__device__ __forceinline__ void pfL2(const void* p) {
    asm volatile("prefetch.global.L2 [%0];" :: "l"(p));
}

// Fused 3-gate fp16 GEMM (HMMA m16n8k16 + ldmatrix), fp32 accumulate.
// 256 threads, 2 CTAs/SM. CTA tile: M=128 x (64 per gate). Warp tile 32m x 32n.
// (R14 mainloop, proven. 64m retiles spill registers -> L2 blowup; do not revisit.)
// Epilogue loads are double-buffered per j-group to hide DRAM latency.
// MODE 0: gi (interleaved) = acc + b_ih  AND  h16 out = GRU step with h=0 (fused iter0)
// MODE 1: GRU step, intermediate: write h16 only
// MODE 2: GRU step, final: write fp32 out only
template <int MODE>
__global__ void __launch_bounds__(NTH, 2)
gru_h(const __half* __restrict__ A16,    // [8192, 2048]  (e16 or h16_in)
      const __half* __restrict__ W16,    // [6144, 2048]
      const float*  __restrict__ b_ih,   // [6144]  (MODE 0)
      const float*  __restrict__ b_hh,   // [6144]
      uint4*        __restrict__ gi,     // written MODE 0, read MODE 1/2
      float*        __restrict__ outf,   // MODE 2
      __half*       __restrict__ out16)  // MODE 0/1
{
    extern __shared__ char smc[];
    const uint32_t sbase = smem_u32(smc);
    const int t = threadIdx.x;
    const int wid = t >> 5, lane = t & 31;
    const int m0 = blockIdx.y * BM;
    const int n0 = blockIdx.x * BNG;
    const int wm  = (wid >> 1) * 32;     // warp m offset (0,32,64,96)
    const int wn2 = (wid & 1) * 32;      // warp n offset within gate (0,32)
    const int lr = lane >> 2;            // 0..7
    const int lc = lane & 3;             // 0..3

    float acc2[3][2][4][4];
#pragma unroll
    for (int g = 0; g < 3; g++)
#pragma unroll
        for (int i = 0; i < 2; i++)
#pragma unroll
            for (int j = 0; j < 4; j++)
#pragma unroll
                for (int c = 0; c < 4; c++) acc2[g][i][j][c] = 0.0f;

    // ---- precomputed swizzled smem offsets ----
    uint32_t soff[10];
#pragma unroll
    for (int i = 0; i < 10; i++) {
        int id = t + NTH * i;
        int row = id >> 3;
        int qb = (id & 7) * 16;
        soff[i] = swz((uint32_t)row * 128 + qb);
    }

    // ldmatrix lane addressing
    const int a_row = lane & 15;
    const int a_kb  = (lane >> 4) * 16;
    const int b_row = (lane & 7) | ((lane & 16) >> 1);
    const int b_kb  = (lane & 8) * 2;

    uint32_t aoff[2], boff[6];
#pragma unroll
    for (int i = 0; i < 2; i++)
        aoff[i] = swz((uint32_t)(wm + i * 16 + a_row) * 128 + a_kb);
#pragma unroll
    for (int nx = 0; nx < 6; nx++) {
        int g = nx >> 1, j2 = nx & 1;
        boff[nx] = swz((uint32_t)(BM + g * BNG + wn2 + j2 * 16 + b_row) * 128 + b_kb);
    }

    auto issue = [&](int stage, int kc) {   // kc in fp16 elems
        uint32_t st = sbase + stage * STAGE_BYTES;
#pragma unroll
        for (int i = 0; i < 10; i++) {
            int id = t + NTH * i;          // 0..2559
            int row = id >> 3;             // 0..319
            int qb = (id & 7) * 16;        // byte offset in row
            const __half* gsrc;
            if (row < BM) {
                gsrc = A16 + (size_t)(m0 + row) * HH_ + kc + (qb >> 1);
            } else {
                int r = row - BM;
                int g = r >> 6, n = r & 63;
                gsrc = W16 + ((size_t)g * HH_ + n0 + n) * HH_ + kc + (qb >> 1);
            }
            cp16(st + soff[i], gsrc);
        }
        asm volatile("cp.async.commit_group;\n" ::: "memory");
    };

    issue(0, 0);

    for (int c = 0; c < NC; c++) {
        asm volatile("cp.async.wait_group 0;\n" ::: "memory");
        __syncthreads();

        // L2 prefetch of epilogue operands, issued once, well before the tail
        if (MODE != 0 && c == NC - 4) {
#pragma unroll
            for (int j = 0; j < 4; j++) {
                int ngl = n0 + wn2 + j * 8 + 2 * lc;
#pragma unroll
                for (int i = 0; i < 2; i++) {
                    int m = m0 + wm + i * 16 + lr;
#pragma unroll
                    for (int half = 0; half < 2; half++) {
                        int mm = m + half * 8;
                        pfL2(gi + (size_t)mm * (HH_ / 2) + (ngl >> 1));
                        pfL2(A16 + (size_t)mm * HH_ + ngl);
                    }
                }
            }
        }

        uint32_t st = sbase + (c & 1) * STAGE_BYTES;

        // fully-pipelined fragment stream across the 4 k16 steps
        uint32_t a[2][2][4];     // [s-slot][i][4]
        uint32_t b[2][4];
        ldsm4(a[0][0], st + aoff[0]);
        ldsm4(a[0][1], st + aoff[1]);
        ldsm4(b[0], st + boff[0]);

#pragma unroll
        for (int s = 0; s < 4; s++) {
            const int cur = s & 1;
            const uint32_t sx = (uint32_t)(s << 5);
            const uint32_t sx1 = (uint32_t)((s + 1) << 5);
#pragma unroll
            for (int nx = 0; nx < 6; nx++) {
                const int bi = nx & 1;
                // prefetch next B fragment group (crossing step boundary)
                if (nx < 5)      ldsm4(b[bi ^ 1], st + (boff[nx + 1] ^ sx));
                else if (s < 3)  ldsm4(b[bi ^ 1], st + (boff[0] ^ sx1));
                // prefetch A fragments for next step
                if (nx == 4 && s < 3) {
                    ldsm4(a[cur ^ 1][0], st + (aoff[0] ^ sx1));
                    ldsm4(a[cur ^ 1][1], st + (aoff[1] ^ sx1));
                }
                const int g = nx >> 1, j2 = nx & 1;
                mma16816(acc2[g][0][2 * j2],     a[cur][0], b[bi][0], b[bi][1]);
                mma16816(acc2[g][0][2 * j2 + 1], a[cur][0], b[bi][2], b[bi][3]);
                mma16816(acc2[g][1][2 * j2],     a[cur][1], b[bi][0], b[bi][1]);
                mma16816(acc2[g][1][2 * j2 + 1], a[cur][1], b[bi][2], b[bi][3]);
            }
            // overlap the next chunk's cp.async issue burst with the MMA stream
            if (s == 0 && c + 1 < NC) issue((c + 1) & 1, (c + 1) * BK);
        }
    }

    // ---------------- Epilogue ----------------
    if (MODE == 0) {
#pragma unroll
        for (int j = 0; j < 4; j++) {
            int ngl = n0 + wn2 + j * 8 + 2 * lc;
            float2 bhr = *(const float2*)(b_hh + ngl);
            float2 bhz = *(const float2*)(b_hh + HH_ + ngl);
            float2 bhn = *(const float2*)(b_hh + 2 * HH_ + ngl);
            float2 bir = *(const float2*)(b_ih + ngl);
            float2 biz = *(const float2*)(b_ih + HH_ + ngl);
            float2 bin = *(const float2*)(b_ih + 2 * HH_ + ngl);
#pragma unroll
            for (int i = 0; i < 2; i++) {
                int m = m0 + wm + i * 16 + lr;
#pragma unroll
                for (int half = 0; half < 2; half++) {
                    int mm = m + half * 8;
                    int o  = half * 2;
                    size_t slot = (size_t)mm * (HH_ / 2) + (ngl >> 1);
                    float grx = acc2[0][i][j][o]     + bir.x;
                    float gry = acc2[0][i][j][o + 1] + bir.y;
                    float gzx = acc2[1][i][j][o]     + biz.x;
                    float gzy = acc2[1][i][j][o + 1] + biz.y;
                    float gnx = acc2[2][i][j][o]     + bin.x;
                    float gny = acc2[2][i][j][o + 1] + bin.y;
                    uint4 v;
                    v.x = h2u(__floats2half2_rn(grx, gry));
                    v.y = h2u(__floats2half2_rn(gzx, gzy));
                    v.z = h2u(__floats2half2_rn(gnx, gny));
                    v.w = 0u;
                    gi[slot] = v;
                    // fused iteration 0 (h = 0)
                    float rx = sigf(grx + bhr.x), ry = sigf(gry + bhr.y);
                    float zx = sigf(gzx + bhz.x), zy = sigf(gzy + bhz.y);
                    float nx = tanha(gnx + rx * bhn.x);
                    float ny = tanha(gny + ry * bhn.y);
                    float hx = (1.0f - zx) * nx;
                    float hy = (1.0f - zy) * ny;
                    *(__half2*)(out16 + (size_t)mm * HH_ + ngl) = __floats2half2_rn(hx, hy);
                }
            }
        }
    } else {
        // Double-buffered epilogue: loads for group j+1 issue before compute of j.
        uint4    vg[2][4];
        uint32_t vh[2][4];
        auto eload = [&](int j, int buf) {
            int ngl = n0 + wn2 + j * 8 + 2 * lc;
#pragma unroll
            for (int p = 0; p < 4; p++) {           // p = i*2 + half
                int i = p >> 1, half = p & 1;
                int mm = m0 + wm + i * 16 + lr + half * 8;
                vg[buf][p] = gi[(size_t)mm * (HH_ / 2) + (ngl >> 1)];
                vh[buf][p] = *(const uint32_t*)(A16 + (size_t)mm * HH_ + ngl);
            }
        };
        eload(0, 0);
#pragma unroll
        for (int j = 0; j < 4; j++) {
            const int buf = j & 1;
            if (j < 3) eload(j + 1, buf ^ 1);

            int ngl = n0 + wn2 + j * 8 + 2 * lc;
            float2 bhr = *(const float2*)(b_hh + ngl);
            float2 bhz = *(const float2*)(b_hh + HH_ + ngl);
            float2 bhn = *(const float2*)(b_hh + 2 * HH_ + ngl);
#pragma unroll
            for (int p = 0; p < 4; p++) {
                int i = p >> 1, half = p & 1;
                int mm = m0 + wm + i * 16 + lr + half * 8;
                int o  = half * 2;
                uint4 v = vg[buf][p];
                float2 gr = __half22float2(u2h(v.x));
                float2 gz = __half22float2(u2h(v.y));
                float2 gn = __half22float2(u2h(v.z));
                float2 hv = __half22float2(u2h(vh[buf][p]));

                float rx = sigf(gr.x + acc2[0][i][j][o]     + bhr.x);
                float ry = sigf(gr.y + acc2[0][i][j][o + 1] + bhr.y);
                float zx = sigf(gz.x + acc2[1][i][j][o]     + bhz.x);
                float zy = sigf(gz.y + acc2[1][i][j][o + 1] + bhz.y);
                float nx = tanha(gn.x + rx * (acc2[2][i][j][o]     + bhn.x));
                float ny = tanha(gn.y + ry * (acc2[2][i][j][o + 1] + bhn.y));

                float hx = nx + zx * (hv.x - nx);
                float hy = ny + zy * (hv.y - ny);

                if (MODE == 1) {
                    *(__half2*)(out16 + (size_t)mm * HH_ + ngl) = __floats2half2_rn(hx, hy);
                } else {
                    *(float2*)(outf + (size_t)mm * HH_ + ngl) = make_float2(hx, hy);
                }
            }
        }
    }
}

// merged float -> half conversion for 3 tensors (single launch)
__global__ void f2h3_kernel(const float* __restrict__ s0, __half* __restrict__ d0, int n0,
                            const float* __restrict__ s1, __half* __restrict__ d1, int n1,
                            const float* __restrict__ s2, __half* __restrict__ d2, int n2)
{
    int j = blockIdx.x * blockDim.x + threadIdx.x;
    const float* s;
    __half* d;
    if (j < n0) { s = s0; d = d0; }
    else if ((j -= n0) < n1) { s = s1; d = d1; }
    else if ((j -= n1) < n2) { s = s2; d = d2; }
    else return;
    float4 v = ((const float4*)s)[j];
    ((__half2*)d)[2 * j]     = __floats2half2_rn(v.x, v.y);
    ((__half2*)d)[2 * j + 1] = __floats2half2_rn(v.z, v.w);
}

extern "C" void kernel_launch(void* const* d_in, const int* in_sizes, int n_in,
                              void* d_out, int out_size)
{
    const float* enc  = (const float*)d_in[0];
    const float* w_ih = (const float*)d_in[1];
    const float* w_hh = (const float*)d_in[2];
    const float* b_ih = (const float*)d_in[3];
    const float* b_hh = (const float*)d_in[4];
    float* out = (float*)d_out;

    cudaFuncSetAttribute(gru_h<0>, cudaFuncAttributeMaxDynamicSharedMemorySize, SMEM_TOTAL);
    cudaFuncSetAttribute(gru_h<1>, cudaFuncAttributeMaxDynamicSharedMemorySize, SMEM_TOTAL);
    cudaFuncSetAttribute(gru_h<2>, cudaFuncAttributeMaxDynamicSharedMemorySize, SMEM_TOTAL);

    uint4* gi;
    __half *h16, *w16i, *w16h, *e16;
    cudaGetSymbolAddress((void**)&gi,   g_gi);
    cudaGetSymbolAddress((void**)&h16,  g_h16);
    cudaGetSymbolAddress((void**)&w16i, g_w16i);
    cudaGetSymbolAddress((void**)&w16h, g_w16h);
    cudaGetSymbolAddress((void**)&e16,  g_e16);
    const size_t HN = (size_t)MB_ * HH_;

    dim3 grid(HH_ / BNG, MB_ / BM);   // (32, 64) = 2048 CTAs

    // convert all operands upfront in one launch
    const int n0 = MB_ * HH_ / 4;        // enc float4s
    const int n1 = K3_ * HH_ / 4;        // w_ih float4s
    const int n2 = K3_ * HH_ / 4;        // w_hh float4s
    f2h3_kernel<<<(n0 + n1 + n2 + 255) / 256, 256>>>(enc, e16, n0,
                                                     w_ih, w16i, n1,
                                                     w_hh, w16h, n2);

    // gi = enc @ w_ih^T + b_ih  (interleaved fp16), fused with iteration 0 -> h16[0]
    gru_h<0><<<grid, NTH, SMEM_TOTAL>>>(e16, w16i, b_ih, b_hh, gi, nullptr, h16);

    // iterations 1..8 (write h16), iteration 9 (write fp32 out)
    int p = 0;
    for (int it = 1; it < NITER - 1; it++) {
        gru_h<1><<<grid, NTH, SMEM_TOTAL>>>(h16 + p * HN, w16h, b_ih, b_hh, gi,
                                            nullptr, h16 + (1 - p) * HN);
        p = 1 - p;
    }
    gru_h<2><<<grid, NTH, SMEM_TOTAL>>>(h16 + p * HN, w16h, b_ih, b_hh, gi, out, nullptr);
}